// round 16
// baseline (speedup 1.0000x reference)
#include <cuda_runtime.h>
#include <cuda_fp16.h>
#include <cstdint>

#define BB   2
#define CC   64
#define HH   256
#define WW   256
#define KK   9
#define ND   3
#define NTAP 27
#define NOFF 54
#define TPX  128         // pixels per main-kernel block
#define NTHR 384         // main kernel threads: 4 producer + 8 consumer warps

typedef unsigned long long ull;
typedef unsigned int u32;

#define BAR_SYNC(id, cnt)   asm volatile("bar.sync %0, %1;"   :: "r"(id), "r"(cnt) : "memory")
#define BAR_ARRIVE(id, cnt) asm volatile("bar.arrive %0, %1;" :: "r"(id), "r"(cnt) : "memory")
// named barrier ids: FULL[i]=1+i, EMPTY[i]=4+i (i=0..2), consumer fence=7
#define BAR_FULL(i)  (1 + (i))
#define BAR_EMPTY(i) (4 + (i))
#define BAR_CONS     7

#define FMA2(d, a, b, c) asm("fma.rn.f32x2 %0, %1, %2, %3;" : "=l"(d) : "l"(a), "l"(b), "l"(c))
#define PACK2(d, lo, hi) asm("mov.b64 %0, {%1, %2};" : "=l"(d) : "f"(lo), "f"(hi))
#define UNPACK2(lo, hi, s) asm("mov.b64 {%0, %1}, %2;" : "=f"(lo), "=f"(hi) : "l"(s))

// m16n8k16 fp16 mma, fp32 accumulate (sm_80 baseline PTX -> HMMA on sm_103)
__device__ __forceinline__ void mma_f16(float* c,
                                        u32 a0, u32 a1, u32 a2, u32 a3,
                                        u32 b0, u32 b1) {
    asm("mma.sync.aligned.m16n8k16.row.col.f32.f16.f16.f32 "
        "{%0,%1,%2,%3}, {%4,%5,%6,%7}, {%8,%9}, {%0,%1,%2,%3};"
        : "+f"(c[0]), "+f"(c[1]), "+f"(c[2]), "+f"(c[3])
        : "r"(a0), "r"(a1), "r"(a2), "r"(a3), "r"(b0), "r"(b1));
}

// ---------------- scratch ----------------------------------------------------
__device__ __half g_xT[(size_t)BB * HH * WW * CC];         // fp16, P(c)-ordered NHWC
__device__ float  g_offT[(size_t)BB * HH * NOFF * WW];     // offsets (bh, ch, w)
__device__ __half g_weffH[(size_t)ND * KK * CC * CC];      // frag-ordered fp16
__device__ __half g_woffH[(size_t)KK * CC * CC];           // offset-conv weights

__device__ __forceinline__ int P_of(int c) {
    return (c >> 4) * 16 + ((c & 7) >> 1) * 4 + ((c >> 3) & 1) * 2 + (c & 1);
}
__device__ __forceinline__ int frag_index_h(int oo, int c) {
    int s = c >> 4, r = c & 15;
    int le = (r & 7) >> 1, hidx = ((r >> 3) << 1) | (r & 1);
    int wn = oo >> 5, nt = (oo >> 3) & 3, g = oo & 7;
    return ((((wn * 4 + s) * 4 + nt) * 32) + g * 4 + le) * 4 + hidx;
}

// ---------------- 1) transpose x -> fragment-ordered fp16 NHWC ----------------
__global__ void transpose_kernel(const float* __restrict__ x) {
    __shared__ float tile[32][33];
    int bh = blockIdx.z;
    int b  = bh / HH, h = bh % HH;
    int w0 = blockIdx.x * 32;
    int c0 = blockIdx.y * 32;
    int tx = threadIdx.x, ty = threadIdx.y;

    #pragma unroll
    for (int j = 0; j < 4; j++) {
        int c = c0 + ty + j * 8;
        tile[ty + j * 8][tx] = x[(((size_t)b * CC + c) * HH + h) * WW + (w0 + tx)];
    }
    __syncthreads();
    #pragma unroll
    for (int j = 0; j < 4; j++) {
        int w = w0 + ty + j * 8;
        int c = c0 + tx;
        g_xT[(((size_t)b * HH + h) * WW + w) * CC + P_of(c)] =
            __float2half(tile[tx][ty + j * 8]);
    }
}

// ---------------- 2a) Weff -> fragment-ordered fp16 ---------------------------
__global__ void weff_kernel(const float* __restrict__ Wd,
                            const float* __restrict__ Wfuse) {
    int idx = blockIdx.x * 256 + threadIdx.x;
    if (idx >= ND * KK * CC * CC) return;
    int oo = idx % CC;
    int c  = (idx / CC) % CC;
    int k  = (idx / (CC * CC)) % KK;
    int i  = idx / (CC * CC * KK);
    float acc = 0.f;
    #pragma unroll 8
    for (int o = 0; o < CC; o++) {
        acc = fmaf(Wfuse[oo * (ND * CC) + i * CC + o],
                   Wd[(((size_t)(i * CC + o) * CC + c) * KK) + k], acc);
    }
    int tap = i * KK + k;
    g_weffH[(size_t)tap * CC * CC + frag_index_h(oo, c)] = __float2half(acc);
}

// ---------------- 2b) Woff -> fragment-ordered fp16 ---------------------------
__global__ void woff_kernel(const float* __restrict__ Woff) {
    int idx = blockIdx.x * 256 + threadIdx.x;
    if (idx >= KK * CC * CC) return;
    int c  = idx % CC;
    int oc = (idx / CC) % CC;
    int k  = idx / (CC * CC);
    float v = (oc < NOFF) ? Woff[(size_t)oc * CC * KK + c * KK + k] : 0.f;
    g_woffH[(size_t)k * CC * CC + frag_index_h(oc, c)] = __float2half(v);
}

// ---------------- 3) offset conv via fp16 mma, swizzled smem -------------------
__global__ __launch_bounds__(256, 2)
void offconv_kernel(const float* __restrict__ boff) {
    extern __shared__ u32 smo[];
    __half* sX = (__half*)smo;

    int bh = blockIdx.y;
    int b  = bh / HH, h = bh % HH;
    int w0 = blockIdx.x * TPX;
    int tid = threadIdx.x;
    int lane = tid & 31, wid = tid >> 5;
    int warp_m = wid >> 1;
    int warp_n = wid & 1;
    int lg = lane >> 2;
    int le = lane & 3;

    const __half* xTrow = g_xT + (size_t)b * HH * WW * CC;

    float acc[2][4][4];
    #pragma unroll
    for (int mt = 0; mt < 2; mt++)
        #pragma unroll
        for (int nt = 0; nt < 4; nt++)
            #pragma unroll
            for (int e = 0; e < 4; e++) acc[mt][nt][e] = 0.f;

    for (int ky = 0; ky < 3; ky++) {
        int row = h + ky - 1;
        bool valid = (row >= 0 && row < HH);
        __half* sXp = sX + (ky & 1) * (130 * 64);

        if (valid) {
            const uint4* src = (const uint4*)(xTrow + (size_t)row * WW * CC);
            for (int t = tid; t < 130 * 8; t += 256) {
                int px = t >> 3, ch = t & 7;
                int w = w0 - 1 + px;
                uint4 val = make_uint4(0u, 0u, 0u, 0u);
                if (w >= 0 && w < WW) val = __ldg(src + (size_t)w * 8 + ch);
                *(uint4*)&sXp[px * 64 + 8 * (ch ^ (px & 7))] = val;
            }
        }
        __syncthreads();

        if (valid) {
            #pragma unroll
            for (int kx = 0; kx < 3; kx++) {
                int k = ky * 3 + kx;
                const uint2* wF2 = (const uint2*)g_woffH + (size_t)k * 1024 + warp_n * 512;
                int abase = warp_m * 32 + kx;
                int rs = (abase + lg) & 7;
                #pragma unroll
                for (int s2 = 0; s2 < 4; s2++) {
                    int sw = (((s2 << 1) + (le >> 1)) ^ rs) * 8 + (le & 1) * 4;
                    uint2 a00 = *(const uint2*)&sXp[(abase + lg)      * 64 + sw];
                    uint2 a01 = *(const uint2*)&sXp[(abase + lg + 8)  * 64 + sw];
                    uint2 a10 = *(const uint2*)&sXp[(abase + lg + 16) * 64 + sw];
                    uint2 a11 = *(const uint2*)&sXp[(abase + lg + 24) * 64 + sw];
                    #pragma unroll
                    for (int nt = 0; nt < 4; nt++) {
                        uint2 bv = __ldg(wF2 + (s2 * 4 + nt) * 32 + lane);
                        mma_f16(acc[0][nt], a00.x, a01.x, a00.y, a01.y, bv.x, bv.y);
                        mma_f16(acc[1][nt], a10.x, a11.x, a10.y, a11.y, bv.x, bv.y);
                    }
                }
            }
        }
    }

    float* sOut = (float*)smo;
    __syncthreads();
    #pragma unroll
    for (int mt = 0; mt < 2; mt++) {
        int px0 = warp_m * 32 + mt * 16 + lg;
        #pragma unroll
        for (int nt = 0; nt < 4; nt++) {
            int oc = warp_n * 32 + nt * 8 + 2 * le;
            float b0 = (oc < NOFF)     ? __ldg(&boff[oc])     : 0.f;
            float b1 = (oc + 1 < NOFF) ? __ldg(&boff[oc + 1]) : 0.f;
            sOut[oc * TPX + px0]           = acc[mt][nt][0] + b0;
            sOut[(oc + 1) * TPX + px0]     = acc[mt][nt][1] + b1;
            sOut[oc * TPX + px0 + 8]       = acc[mt][nt][2] + b0;
            sOut[(oc + 1) * TPX + px0 + 8] = acc[mt][nt][3] + b1;
        }
    }
    __syncthreads();
    {
        int oc = tid >> 2;
        int f0 = tid & 3;
        if (oc < NOFF) {
            float4* op = (float4*)(g_offT + ((size_t)bh * NOFF + oc) * WW + w0);
            const float4* sp = (const float4*)(sOut + oc * TPX);
            #pragma unroll
            for (int j = 0; j < 8; j++) op[f0 + j * 4] = sp[f0 + j * 4];
        }
    }
}

// ---------------- 4) main: 4 producer + 8 consumer warps, 24 warps/SM ---------
// smem: sS 3*128*64 halves (49152B) + sG 2*128*8 floats (8192B) = 57344B
#define SMF_G   ((3 * TPX * 64 * 2) / 4)
#define SM_TOTAL (3 * TPX * 64 * 2 + 2 * TPX * 8 * 4)

__global__ __launch_bounds__(NTHR, 2)
void main_kernel(float* __restrict__ out) {
    extern __shared__ float sm[];
    float* sG = sm + SMF_G;

    int bh = blockIdx.y;
    int b  = bh / HH, h = bh % HH;
    int w0 = blockIdx.x * TPX;
    int tid = threadIdx.x;
    int lane = tid & 31, wid = tid >> 5;

    const char*  xTb  = (const char*)(g_xT + (size_t)b * HH * WW * CC);
    const float* offb = g_offT + (size_t)bh * NOFF * WW + w0;

    if (tid < 128) {
        // ===================== PRODUCER (warps 0-3) ==========================
        int grp = tid >> 3;       // 16 groups, 8 px each
        int f   = tid & 7;        // 16B fp16 chunk lane

        auto setup = [&](int tap, int buf) {
            int px = tid;
            int i = tap / KK, k = tap - i * KK;
            int d = 1 << i;
            float dy = __ldg(offb + (size_t)(i * 18 + 2 * k) * WW + px);
            float dx = __ldg(offb + (size_t)(i * 18 + 2 * k + 1) * WW + px);
            float ys  = (float)h + (float)((k / 3 - 1) * d) + dy;
            float xsf = (float)(w0 + px) + (float)((k % 3 - 1) * d) + dx;
            float y0f = floorf(ys), x0f = floorf(xsf);
            float wy1 = ys - y0f, wx1 = xsf - x0f, wy0 = 1.f - wy1, wx0 = 1.f - wx1;
            float y1f = y0f + 1.f, x1f = x0f + 1.f;
            float vy0 = (y0f >= 0.f && y0f <= 255.f) ? 1.f : 0.f;
            float vy1 = (y1f >= 0.f && y1f <= 255.f) ? 1.f : 0.f;
            float vx0 = (x0f >= 0.f && x0f <= 255.f) ? 1.f : 0.f;
            float vx1 = (x1f >= 0.f && x1f <= 255.f) ? 1.f : 0.f;
            u32 iy0 = (u32)(int)fminf(fmaxf(y0f, 0.f), 255.f);
            u32 iy1 = (u32)(int)fminf(fmaxf(y1f, 0.f), 255.f);
            u32 ix0 = (u32)(int)fminf(fmaxf(x0f, 0.f), 255.f);
            u32 ix1 = (u32)(int)fminf(fmaxf(x1f, 0.f), 255.f);
            uint4 o;
            o.x = ((iy0 * WW + ix0) * CC) * 2u;
            o.y = ((iy0 * WW + ix1) * CC) * 2u;
            o.z = ((iy1 * WW + ix0) * CC) * 2u;
            o.w = ((iy1 * WW + ix1) * CC) * 2u;
            float4 cw = make_float4(wy0 * wx0 * vy0 * vx0, wy0 * wx1 * vy0 * vx1,
                                    wy1 * wx0 * vy1 * vx0, wy1 * wx1 * vy1 * vx1);
            *(uint4*) &sG[(buf * TPX + px) * 8]     = o;
            *(float4*)&sG[(buf * TPX + px) * 8 + 4] = cw;
        };

        setup(0, 0);
        __syncwarp();   // sG handoff is intra-8-thread-group

        for (int tap = 0; tap < NTAP; tap++) {
            int ps = tap % 3;
            int pg = tap & 1;
            __half* sS16 = (__half*)sm + ps * (TPX * 64);
            const float* gbase = &sG[(pg * TPX + grp * 8) * 8];

            float4 cwb[2];
            uint4  da[2], db[2], dc[2], dd[2];
            {
                uint4 o0 = *(const uint4*)(gbase);
                cwb[0]   = *(const float4*)(gbase + 4);
                da[0] = __ldg((const uint4*)(xTb + o0.x) + f);
                db[0] = __ldg((const uint4*)(xTb + o0.y) + f);
                dc[0] = __ldg((const uint4*)(xTb + o0.z) + f);
                dd[0] = __ldg((const uint4*)(xTb + o0.w) + f);
                uint4 o1 = *(const uint4*)(gbase + 8);
                cwb[1]   = *(const float4*)(gbase + 12);
                da[1] = __ldg((const uint4*)(xTb + o1.x) + f);
                db[1] = __ldg((const uint4*)(xTb + o1.y) + f);
                dc[1] = __ldg((const uint4*)(xTb + o1.z) + f);
                dd[1] = __ldg((const uint4*)(xTb + o1.w) + f);
            }

            if (tap + 1 < NTAP) setup(tap + 1, 1 - pg);

            if (tap >= 3) BAR_SYNC(BAR_EMPTY(ps), NTHR);

            #pragma unroll
            for (int j = 0; j < 8; j++) {
                int sl = j & 1;
                float4 cw = cwb[sl];
                uint4 A = da[sl], B = db[sl], C = dc[sl], D = dd[sl];

                if (j < 6) {
                    uint4 on = *(const uint4*)(gbase + (j + 2) * 8);
                    cwb[sl]  = *(const float4*)(gbase + (j + 2) * 8 + 4);
                    da[sl] = __ldg((const uint4*)(xTb + on.x) + f);
                    db[sl] = __ldg((const uint4*)(xTb + on.y) + f);
                    dc[sl] = __ldg((const uint4*)(xTb + on.z) + f);
                    dd[sl] = __ldg((const uint4*)(xTb + on.w) + f);
                }

                ull CW0, CW1, CW2, CW3, ZERO = 0ull;
                PACK2(CW0, cw.x, cw.x);
                PACK2(CW1, cw.y, cw.y);
                PACK2(CW2, cw.z, cw.z);
                PACK2(CW3, cw.w, cw.w);
                const __half2* ha = (const __half2*)&A;
                const __half2* hb = (const __half2*)&B;
                const __half2* hc = (const __half2*)&C;
                const __half2* hd = (const __half2*)&D;
                u32 outw[4];
                #pragma unroll
                for (int m = 0; m < 4; m++) {
                    float2 va = __half22float2(ha[m]);
                    float2 vb = __half22float2(hb[m]);
                    float2 vc = __half22float2(hc[m]);
                    float2 vd = __half22float2(hd[m]);
                    ull A2, B2, C2, D2, R;
                    PACK2(A2, va.x, va.y);
                    PACK2(B2, vb.x, vb.y);
                    PACK2(C2, vc.x, vc.y);
                    PACK2(D2, vd.x, vd.y);
                    FMA2(R, A2, CW0, ZERO);
                    FMA2(R, B2, CW1, R);
                    FMA2(R, C2, CW2, R);
                    FMA2(R, D2, CW3, R);
                    float r0, r1;
                    UNPACK2(r0, r1, R);
                    __half2 hr = __floats2half2_rn(r0, r1);
                    outw[m] = *(u32*)&hr;
                }
                *(uint4*)&sS16[(grp * 8 + j) * 64 + 8 * (f ^ j)] =
                    make_uint4(outw[0], outw[1], outw[2], outw[3]);
            }

            BAR_ARRIVE(BAR_FULL(ps), NTHR);
            __syncwarp();
        }
    } else {
        // ===================== CONSUMER (warps 4-11): 16px x 64oo each =======
        int cwarp = wid - 4;          // 0..7
        int lg = lane >> 2;
        int le = lane & 3;
        int arow = cwarp * 16 + lg;

        float acc[8][4];
        #pragma unroll
        for (int nt = 0; nt < 8; nt++)
            #pragma unroll
            for (int e = 0; e < 4; e++) acc[nt][e] = 0.f;

        for (int tap = 0; tap < NTAP; tap++) {
            int ps = tap % 3;
            __half* sS16 = (__half*)sm + ps * (TPX * 64);

            BAR_SYNC(BAR_FULL(ps), NTHR);

            const uint2* wB = (const uint2*)g_weffH + (size_t)tap * 1024;
            #pragma unroll
            for (int s2 = 0; s2 < 4; s2++) {
                int sw = (((s2 << 1) + (le >> 1)) ^ lg) * 8 + (le & 1) * 4;
                uint2 a00 = *(const uint2*)&sS16[(arow)     * 64 + sw];
                uint2 a01 = *(const uint2*)&sS16[(arow + 8) * 64 + sw];
                #pragma unroll
                for (int nt2 = 0; nt2 < 8; nt2++) {
                    int bidx = (((nt2 >> 2) * 4 + s2) * 4 + (nt2 & 3)) * 32 + lane;
                    uint2 bv = __ldg(wB + bidx);
                    mma_f16(acc[nt2], a00.x, a01.x, a00.y, a01.y, bv.x, bv.y);
                }
            }

            if (tap + 3 < NTAP)
                BAR_ARRIVE(BAR_EMPTY(ps), NTHR);
        }

        BAR_SYNC(BAR_CONS, 256);

        // sOut = sm[0..32KB) = sS buffers 0,1 (consumed at taps 24,25; tap 26
        // wrote buffer 2) -> safe.
        float* sOut = sm;
        {
            int px0 = cwarp * 16 + lg;
            #pragma unroll
            for (int nt2 = 0; nt2 < 8; nt2++) {
                int oo = (nt2 >> 2) * 32 + (nt2 & 3) * 8 + 2 * le;
                sOut[oo * TPX + px0]           = acc[nt2][0];
                sOut[(oo + 1) * TPX + px0]     = acc[nt2][1];
                sOut[oo * TPX + px0 + 8]       = acc[nt2][2];
                sOut[(oo + 1) * TPX + px0 + 8] = acc[nt2][3];
            }
        }
    }

    __syncthreads();
    {
        const float4* sp = (const float4*)sm;    // 64 rows x 32 float4
        for (int t = tid; t < CC * (TPX / 4); t += NTHR) {
            int row = t >> 5;           // oo
            int f0  = t & 31;           // float4 index within row
            out[0] = out[0];            // no-op guard removed by compiler
            ((float4*)(out + (((size_t)(b * CC + row) * HH + h) * WW + w0)))[f0]
                = sp[row * 32 + f0];
        }
    }
}

// ---------------- launch ------------------------------------------------------
extern "C" void kernel_launch(void* const* d_in, const int* in_sizes, int n_in,
                              void* d_out, int out_size) {
    const float* x     = (const float*)d_in[0];
    const float* Woff  = (const float*)d_in[1];
    const float* boff  = (const float*)d_in[2];
    const float* Wd    = (const float*)d_in[3];
    const float* Wfuse = (const float*)d_in[4];
    float* out = (float*)d_out;

    int smem_main = SM_TOTAL;                 // 57344
    int smem_off  = 2 * 130 * 64 * 2;         // 33280
    static int smem_set = 0;
    if (!smem_set) {
        cudaFuncSetAttribute(main_kernel,
                             cudaFuncAttributeMaxDynamicSharedMemorySize, smem_main);
        cudaFuncSetAttribute(offconv_kernel,
                             cudaFuncAttributeMaxDynamicSharedMemorySize, smem_off);
        smem_set = 1;
    }

    transpose_kernel<<<dim3(WW / 32, CC / 32, BB * HH), dim3(32, 8)>>>(x);
    weff_kernel<<<(ND * KK * CC * CC + 255) / 256, 256>>>(Wd, Wfuse);
    woff_kernel<<<(KK * CC * CC + 255) / 256, 256>>>(Woff);
    offconv_kernel<<<dim3(WW / TPX, BB * HH), 256, smem_off>>>(boff);
    main_kernel<<<dim3(WW / TPX, BB * HH), NTHR, smem_main>>>(out);
}

// round 17
// speedup vs baseline: 1.1060x; 1.1060x over previous
#include <cuda_runtime.h>
#include <cuda_fp16.h>
#include <cstdint>

#define BB   2
#define CC   64
#define HH   256
#define WW   256
#define KK   9
#define ND   3
#define NTAP 27
#define NOFF 54
#define TPX  128         // pixels per main-kernel block

typedef unsigned long long ull;
typedef unsigned int u32;

#define BAR_SYNC(id, cnt)   asm volatile("bar.sync %0, %1;"   :: "r"(id), "r"(cnt) : "memory")
#define BAR_ARRIVE(id, cnt) asm volatile("bar.arrive %0, %1;" :: "r"(id), "r"(cnt) : "memory")
// named barrier ids: FULL[i]=1+i, EMPTY[i]=4+i (i=0..2), consumer fence=7
#define BAR_FULL(i)  (1 + (i))
#define BAR_EMPTY(i) (4 + (i))
#define BAR_CONS     7

#define FMA2(d, a, b, c) asm("fma.rn.f32x2 %0, %1, %2, %3;" : "=l"(d) : "l"(a), "l"(b), "l"(c))
#define PACK2(d, lo, hi) asm("mov.b64 %0, {%1, %2};" : "=l"(d) : "f"(lo), "f"(hi))
#define UNPACK2(lo, hi, s) asm("mov.b64 {%0, %1}, %2;" : "=f"(lo), "=f"(hi) : "l"(s))

// m16n8k16 fp16 mma, fp32 accumulate (sm_80 baseline PTX -> HMMA on sm_103)
__device__ __forceinline__ void mma_f16(float* c,
                                        u32 a0, u32 a1, u32 a2, u32 a3,
                                        u32 b0, u32 b1) {
    asm("mma.sync.aligned.m16n8k16.row.col.f32.f16.f16.f32 "
        "{%0,%1,%2,%3}, {%4,%5,%6,%7}, {%8,%9}, {%0,%1,%2,%3};"
        : "+f"(c[0]), "+f"(c[1]), "+f"(c[2]), "+f"(c[3])
        : "r"(a0), "r"(a1), "r"(a2), "r"(a3), "r"(b0), "r"(b1));
}

// ---------------- scratch ----------------------------------------------------
__device__ __half g_xT[(size_t)BB * HH * WW * CC];         // fp16, P(c)-ordered NHWC
__device__ __half g_weffH[(size_t)ND * KK * CC * CC];      // frag-ordered fp16
__device__ __half g_woffH[(size_t)KK * CC * CC];           // offset-conv weights

__device__ __forceinline__ int P_of(int c) {
    return (c >> 4) * 16 + ((c & 7) >> 1) * 4 + ((c >> 3) & 1) * 2 + (c & 1);
}
__device__ __forceinline__ int frag_index_h(int oo, int c) {
    int s = c >> 4, r = c & 15;
    int le = (r & 7) >> 1, hidx = ((r >> 3) << 1) | (r & 1);
    int wn = oo >> 5, nt = (oo >> 3) & 3, g = oo & 7;
    return ((((wn * 4 + s) * 4 + nt) * 32) + g * 4 + le) * 4 + hidx;
}

// ---------------- 1) transpose x -> fragment-ordered fp16 NHWC ----------------
__global__ void transpose_kernel(const float* __restrict__ x) {
    __shared__ float tile[32][33];
    int bh = blockIdx.z;
    int b  = bh / HH, h = bh % HH;
    int w0 = blockIdx.x * 32;
    int c0 = blockIdx.y * 32;
    int tx = threadIdx.x, ty = threadIdx.y;

    #pragma unroll
    for (int j = 0; j < 4; j++) {
        int c = c0 + ty + j * 8;
        tile[ty + j * 8][tx] = x[(((size_t)b * CC + c) * HH + h) * WW + (w0 + tx)];
    }
    __syncthreads();
    #pragma unroll
    for (int j = 0; j < 4; j++) {
        int w = w0 + ty + j * 8;
        int c = c0 + tx;
        g_xT[(((size_t)b * HH + h) * WW + w) * CC + P_of(c)] =
            __float2half(tile[tx][ty + j * 8]);
    }
}

// ---------------- 2a) Weff -> fragment-ordered fp16 ---------------------------
__global__ void weff_kernel(const float* __restrict__ Wd,
                            const float* __restrict__ Wfuse) {
    int idx = blockIdx.x * 256 + threadIdx.x;
    if (idx >= ND * KK * CC * CC) return;
    int oo = idx % CC;
    int c  = (idx / CC) % CC;
    int k  = (idx / (CC * CC)) % KK;
    int i  = idx / (CC * CC * KK);
    float acc = 0.f;
    #pragma unroll 8
    for (int o = 0; o < CC; o++) {
        acc = fmaf(Wfuse[oo * (ND * CC) + i * CC + o],
                   Wd[(((size_t)(i * CC + o) * CC + c) * KK) + k], acc);
    }
    int tap = i * KK + k;
    g_weffH[(size_t)tap * CC * CC + frag_index_h(oo, c)] = __float2half(acc);
}

// ---------------- 2b) Woff -> fragment-ordered fp16 ---------------------------
__global__ void woff_kernel(const float* __restrict__ Woff) {
    int idx = blockIdx.x * 256 + threadIdx.x;
    if (idx >= KK * CC * CC) return;
    int c  = idx % CC;
    int oc = (idx / CC) % CC;
    int k  = idx / (CC * CC);
    float v = (oc < NOFF) ? Woff[(size_t)oc * CC * KK + c * KK + k] : 0.f;
    g_woffH[(size_t)k * CC * CC + frag_index_h(oc, c)] = __float2half(v);
}

// ---------------- 3) FUSED main: offconv phase + producer/consumer phase ------
// smem floats: sS 3*128*64 halves = [0, 12288)   (phase 0 reuses as sX staging)
//              sG 2*128*8        = [12288, 14336)
//              soff 64*128       = [14336, 22528)
// total 22528 floats = 90112 B -> 2 CTAs/SM
#define SMF_G    12288
#define SMF_OFF  14336
#define SM_TOTAL (22528 * 4)

__global__ __launch_bounds__(256, 2)
void main_kernel(float* __restrict__ out, const float* __restrict__ boff) {
    extern __shared__ float sm[];
    float* sG   = sm + SMF_G;
    float* soff = sm + SMF_OFF;

    int bh = blockIdx.y;
    int b  = bh / HH, h = bh % HH;
    int w0 = blockIdx.x * TPX;
    int tid = threadIdx.x;
    int lane = tid & 31, wid = tid >> 5;

    const char*   xTb   = (const char*)(g_xT + (size_t)b * HH * WW * CC);
    const __half* xTrow = g_xT + (size_t)b * HH * WW * CC;

    // =================== PHASE 0: offset conv -> soff (smem) ==================
    {
        __half* sX = (__half*)sm;      // 2 x 130 x 64 halves, inside sS region
        int warp_m = wid >> 1;
        int warp_n = wid & 1;
        int lg = lane >> 2;
        int le = lane & 3;

        float acc[2][4][4];
        #pragma unroll
        for (int mt = 0; mt < 2; mt++)
            #pragma unroll
            for (int nt = 0; nt < 4; nt++)
                #pragma unroll
                for (int e = 0; e < 4; e++) acc[mt][nt][e] = 0.f;

        for (int ky = 0; ky < 3; ky++) {
            int row = h + ky - 1;
            bool valid = (row >= 0 && row < HH);
            __half* sXp = sX + (ky & 1) * (130 * 64);

            if (valid) {
                const uint4* src = (const uint4*)(xTrow + (size_t)row * WW * CC);
                for (int t = tid; t < 130 * 8; t += 256) {
                    int px = t >> 3, ch = t & 7;
                    int w = w0 - 1 + px;
                    uint4 val = make_uint4(0u, 0u, 0u, 0u);
                    if (w >= 0 && w < WW) val = __ldg(src + (size_t)w * 8 + ch);
                    *(uint4*)&sXp[px * 64 + 8 * (ch ^ (px & 7))] = val;
                }
            }
            __syncthreads();

            if (valid) {
                #pragma unroll
                for (int kx = 0; kx < 3; kx++) {
                    int k = ky * 3 + kx;
                    const uint2* wF2 = (const uint2*)g_woffH + (size_t)k * 1024 + warp_n * 512;
                    int abase = warp_m * 32 + kx;
                    int rs = (abase + lg) & 7;
                    #pragma unroll
                    for (int s2 = 0; s2 < 4; s2++) {
                        int sw = (((s2 << 1) + (le >> 1)) ^ rs) * 8 + (le & 1) * 4;
                        uint2 a00 = *(const uint2*)&sXp[(abase + lg)      * 64 + sw];
                        uint2 a01 = *(const uint2*)&sXp[(abase + lg + 8)  * 64 + sw];
                        uint2 a10 = *(const uint2*)&sXp[(abase + lg + 16) * 64 + sw];
                        uint2 a11 = *(const uint2*)&sXp[(abase + lg + 24) * 64 + sw];
                        #pragma unroll
                        for (int nt = 0; nt < 4; nt++) {
                            uint2 bv = __ldg(wF2 + (s2 * 4 + nt) * 32 + lane);
                            mma_f16(acc[0][nt], a00.x, a01.x, a00.y, a01.y, bv.x, bv.y);
                            mma_f16(acc[1][nt], a10.x, a11.x, a10.y, a11.y, bv.x, bv.y);
                        }
                    }
                }
            }
        }

        // epilogue: frags(+bias) -> soff[oc][px]  (no global round-trip)
        __syncthreads();   // mma reads of sX done (paranoia; regions disjoint ok)
        #pragma unroll
        for (int mt = 0; mt < 2; mt++) {
            int px0 = warp_m * 32 + mt * 16 + lg;
            #pragma unroll
            for (int nt = 0; nt < 4; nt++) {
                int oc = warp_n * 32 + nt * 8 + 2 * le;
                float b0 = (oc < NOFF)     ? __ldg(&boff[oc])     : 0.f;
                float b1 = (oc + 1 < NOFF) ? __ldg(&boff[oc + 1]) : 0.f;
                soff[oc * TPX + px0]           = acc[mt][nt][0] + b0;
                soff[(oc + 1) * TPX + px0]     = acc[mt][nt][1] + b1;
                soff[oc * TPX + px0 + 8]       = acc[mt][nt][2] + b0;
                soff[(oc + 1) * TPX + px0 + 8] = acc[mt][nt][3] + b1;
            }
        }
        __syncthreads();   // soff visible to all before phase 1
    }

    // =================== PHASE 1: warp-specialized deformable GEMM ============
    if (tid < 128) {
        // ---------------------- PRODUCER (warps 0-3) --------------------------
        int grp = tid >> 3;       // 16 groups, 8 px each
        int f   = tid & 7;        // 16B fp16 chunk lane

        auto setup = [&](int tap, int buf) {
            int px = tid;
            int i = tap / KK, k = tap - i * KK;
            int d = 1 << i;
            float dy = soff[(i * 18 + 2 * k) * TPX + px];
            float dx = soff[(i * 18 + 2 * k + 1) * TPX + px];
            float ys  = (float)h + (float)((k / 3 - 1) * d) + dy;
            float xsf = (float)(w0 + px) + (float)((k % 3 - 1) * d) + dx;
            float y0f = floorf(ys), x0f = floorf(xsf);
            float wy1 = ys - y0f, wx1 = xsf - x0f, wy0 = 1.f - wy1, wx0 = 1.f - wx1;
            float y1f = y0f + 1.f, x1f = x0f + 1.f;
            float vy0 = (y0f >= 0.f && y0f <= 255.f) ? 1.f : 0.f;
            float vy1 = (y1f >= 0.f && y1f <= 255.f) ? 1.f : 0.f;
            float vx0 = (x0f >= 0.f && x0f <= 255.f) ? 1.f : 0.f;
            float vx1 = (x1f >= 0.f && x1f <= 255.f) ? 1.f : 0.f;
            u32 iy0 = (u32)(int)fminf(fmaxf(y0f, 0.f), 255.f);
            u32 iy1 = (u32)(int)fminf(fmaxf(y1f, 0.f), 255.f);
            u32 ix0 = (u32)(int)fminf(fmaxf(x0f, 0.f), 255.f);
            u32 ix1 = (u32)(int)fminf(fmaxf(x1f, 0.f), 255.f);
            uint4 o;
            o.x = ((iy0 * WW + ix0) * CC) * 2u;
            o.y = ((iy0 * WW + ix1) * CC) * 2u;
            o.z = ((iy1 * WW + ix0) * CC) * 2u;
            o.w = ((iy1 * WW + ix1) * CC) * 2u;
            float4 cw = make_float4(wy0 * wx0 * vy0 * vx0, wy0 * wx1 * vy0 * vx1,
                                    wy1 * wx0 * vy1 * vx0, wy1 * wx1 * vy1 * vx1);
            *(uint4*) &sG[(buf * TPX + px) * 8]     = o;
            *(float4*)&sG[(buf * TPX + px) * 8 + 4] = cw;
        };

        setup(0, 0);
        __syncwarp();   // sG handoff is intra-8-thread-group

        for (int tap = 0; tap < NTAP; tap++) {
            int ps = tap % 3;
            int pg = tap & 1;
            __half* sS16 = (__half*)sm + ps * (TPX * 64);
            const float* gbase = &sG[(pg * TPX + grp * 8) * 8];

            float4 cwb[2];
            uint4  da[2], db[2], dc[2], dd[2];
            {
                uint4 o0 = *(const uint4*)(gbase);
                cwb[0]   = *(const float4*)(gbase + 4);
                da[0] = __ldg((const uint4*)(xTb + o0.x) + f);
                db[0] = __ldg((const uint4*)(xTb + o0.y) + f);
                dc[0] = __ldg((const uint4*)(xTb + o0.z) + f);
                dd[0] = __ldg((const uint4*)(xTb + o0.w) + f);
                uint4 o1 = *(const uint4*)(gbase + 8);
                cwb[1]   = *(const float4*)(gbase + 12);
                da[1] = __ldg((const uint4*)(xTb + o1.x) + f);
                db[1] = __ldg((const uint4*)(xTb + o1.y) + f);
                dc[1] = __ldg((const uint4*)(xTb + o1.z) + f);
                dd[1] = __ldg((const uint4*)(xTb + o1.w) + f);
            }

            if (tap + 1 < NTAP) setup(tap + 1, 1 - pg);

            if (tap >= 3) BAR_SYNC(BAR_EMPTY(ps), 256);

            #pragma unroll
            for (int j = 0; j < 8; j++) {
                int sl = j & 1;
                float4 cw = cwb[sl];
                uint4 A = da[sl], B = db[sl], C = dc[sl], D = dd[sl];

                if (j < 6) {
                    uint4 on = *(const uint4*)(gbase + (j + 2) * 8);
                    cwb[sl]  = *(const float4*)(gbase + (j + 2) * 8 + 4);
                    da[sl] = __ldg((const uint4*)(xTb + on.x) + f);
                    db[sl] = __ldg((const uint4*)(xTb + on.y) + f);
                    dc[sl] = __ldg((const uint4*)(xTb + on.z) + f);
                    dd[sl] = __ldg((const uint4*)(xTb + on.w) + f);
                }

                ull CW0, CW1, CW2, CW3, ZERO = 0ull;
                PACK2(CW0, cw.x, cw.x);
                PACK2(CW1, cw.y, cw.y);
                PACK2(CW2, cw.z, cw.z);
                PACK2(CW3, cw.w, cw.w);
                const __half2* ha = (const __half2*)&A;
                const __half2* hb = (const __half2*)&B;
                const __half2* hc = (const __half2*)&C;
                const __half2* hd = (const __half2*)&D;
                u32 outw[4];
                #pragma unroll
                for (int m = 0; m < 4; m++) {
                    float2 va = __half22float2(ha[m]);
                    float2 vb = __half22float2(hb[m]);
                    float2 vc = __half22float2(hc[m]);
                    float2 vd = __half22float2(hd[m]);
                    ull A2, B2, C2, D2, R;
                    PACK2(A2, va.x, va.y);
                    PACK2(B2, vb.x, vb.y);
                    PACK2(C2, vc.x, vc.y);
                    PACK2(D2, vd.x, vd.y);
                    FMA2(R, A2, CW0, ZERO);
                    FMA2(R, B2, CW1, R);
                    FMA2(R, C2, CW2, R);
                    FMA2(R, D2, CW3, R);
                    float r0, r1;
                    UNPACK2(r0, r1, R);
                    __half2 hr = __floats2half2_rn(r0, r1);
                    outw[m] = *(u32*)&hr;
                }
                *(uint4*)&sS16[(grp * 8 + j) * 64 + 8 * (f ^ j)] =
                    make_uint4(outw[0], outw[1], outw[2], outw[3]);
            }

            BAR_ARRIVE(BAR_FULL(ps), 256);
            __syncwarp();   // guards sG[1-pg] for next iteration (intra-group)
        }
    } else {
        // ---------------------- CONSUMER (warps 4-7) --------------------------
        int cwarp = wid - 4;
        int lg = lane >> 2;
        int le = lane & 3;
        int arow = cwarp * 32 + lg;

        float acc[2][8][4];
        #pragma unroll
        for (int mt = 0; mt < 2; mt++)
            #pragma unroll
            for (int nt = 0; nt < 8; nt++)
                #pragma unroll
                for (int e = 0; e < 4; e++) acc[mt][nt][e] = 0.f;

        for (int tap = 0; tap < NTAP; tap++) {
            int ps = tap % 3;
            __half* sS16 = (__half*)sm + ps * (TPX * 64);

            BAR_SYNC(BAR_FULL(ps), 256);

            const uint2* wB = (const uint2*)g_weffH + (size_t)tap * 1024;
            #pragma unroll
            for (int s2 = 0; s2 < 4; s2++) {
                int sw = (((s2 << 1) + (le >> 1)) ^ lg) * 8 + (le & 1) * 4;
                uint2 a00 = *(const uint2*)&sS16[(arow)      * 64 + sw];
                uint2 a01 = *(const uint2*)&sS16[(arow + 8)  * 64 + sw];
                uint2 a10 = *(const uint2*)&sS16[(arow + 16) * 64 + sw];
                uint2 a11 = *(const uint2*)&sS16[(arow + 24) * 64 + sw];
                #pragma unroll
                for (int nt2 = 0; nt2 < 8; nt2++) {
                    int bidx = (((nt2 >> 2) * 4 + s2) * 4 + (nt2 & 3)) * 32 + lane;
                    uint2 bv = __ldg(wB + bidx);
                    mma_f16(acc[0][nt2], a00.x, a01.x, a00.y, a01.y, bv.x, bv.y);
                    mma_f16(acc[1][nt2], a10.x, a11.x, a10.y, a11.y, bv.x, bv.y);
                }
            }

            if (tap + 3 < NTAP)
                BAR_ARRIVE(BAR_EMPTY(ps), 256);
        }

        BAR_SYNC(BAR_CONS, 128);

        // sOut = sm[0..32KB) = sS buffers 0,1 (consumed at taps 24,25; tap 26
        // wrote buffer 2) -> safe.
        float* sOut = sm;
        #pragma unroll
        for (int mt = 0; mt < 2; mt++) {
            int px0 = cwarp * 32 + mt * 16 + lg;
            #pragma unroll
            for (int nt2 = 0; nt2 < 8; nt2++) {
                int oo = (nt2 >> 2) * 32 + (nt2 & 3) * 8 + 2 * le;
                sOut[oo * TPX + px0]           = acc[mt][nt2][0];
                sOut[(oo + 1) * TPX + px0]     = acc[mt][nt2][1];
                sOut[oo * TPX + px0 + 8]       = acc[mt][nt2][2];
                sOut[(oo + 1) * TPX + px0 + 8] = acc[mt][nt2][3];
            }
        }
    }

    __syncthreads();
    {
        float* sOut = sm;
        int row = tid >> 2;
        int f0  = tid & 3;
        float4* op = (float4*)(out + (((size_t)(b * CC + row) * HH + h) * WW + w0));
        const float4* sp = (const float4*)(sOut + row * TPX);
        #pragma unroll
        for (int j = 0; j < 8; j++) op[f0 + j * 4] = sp[f0 + j * 4];
    }
}

// ---------------- launch ------------------------------------------------------
extern "C" void kernel_launch(void* const* d_in, const int* in_sizes, int n_in,
                              void* d_out, int out_size) {
    const float* x     = (const float*)d_in[0];
    const float* Woff  = (const float*)d_in[1];
    const float* boff  = (const float*)d_in[2];
    const float* Wd    = (const float*)d_in[3];
    const float* Wfuse = (const float*)d_in[4];
    float* out = (float*)d_out;

    static int smem_set = 0;
    if (!smem_set) {
        cudaFuncSetAttribute(main_kernel,
                             cudaFuncAttributeMaxDynamicSharedMemorySize, SM_TOTAL);
        smem_set = 1;
    }

    transpose_kernel<<<dim3(WW / 32, CC / 32, BB * HH), dim3(32, 8)>>>(x);
    weff_kernel<<<(ND * KK * CC * CC + 255) / 256, 256>>>(Wd, Wfuse);
    woff_kernel<<<(KK * CC * CC + 255) / 256, 256>>>(Woff);
    main_kernel<<<dim3(WW / TPX, BB * HH), 256, SM_TOTAL>>>(out, boff);
}